// round 2
// baseline (speedup 1.0000x reference)
#include <cuda_runtime.h>
#include <cstdint>

// Problem constants (fixed by the dataset)
#define NN 100000
#define EE 1600000
#define IND 128
#define HID 64
#define OUTD 40

// ---------------- scratch (device globals; no allocation allowed) -----------
__device__ float g_bufA[(size_t)NN * HID];   // gemm outputs (h1, then h2)
__device__ float g_bufB[(size_t)NN * HID];   // gather outputs (o1, then emb)
__device__ int   g_cnt[NN];
__device__ int   g_rowptr[NN + 1];
__device__ int   g_cursor[NN];
__device__ int   g_col[EE];
__device__ float g_dinv[NN];
__device__ int   g_bsum[256];
__device__ int   g_is64;

// ---------------- dtype detection for edge_index (int64 vs int32) ----------
__global__ void detect_kernel(const int* __restrict__ p) {
    if (blockIdx.x == 0 && threadIdx.x == 0) {
        int all0 = 1;
        for (int i = 1; i < 129; i += 2) {
            if (p[i] != 0) { all0 = 0; break; }
        }
        g_is64 = all0;   // node ids < 2^31, so an int64 view has zero hi-words
    }
}

__device__ __forceinline__ int load_idx(const void* p, long long i, int is64) {
    if (is64) return (int)((const long long*)p)[i];
    return ((const int*)p)[i];
}

// ---------------- degree / CSR build ----------------------------------------
__global__ void zero_cnt_kernel(int n) {
    int i = blockIdx.x * blockDim.x + threadIdx.x;
    if (i < n) g_cnt[i] = 0;
}

__global__ void count_kernel(const void* __restrict__ ei, int E) {
    int e = blockIdx.x * blockDim.x + threadIdx.x;
    if (e >= E) return;
    int is64 = g_is64;
    int d = load_idx(ei, (long long)E + e, is64);   // dst row of edge_index
    atomicAdd(&g_cnt[d], 1);
}

__global__ void scan1_kernel(int n) {
    __shared__ int s[1024];
    int i = blockIdx.x * 1024 + threadIdx.x;
    int v = (i < n) ? g_cnt[i] : 0;
    s[threadIdx.x] = v;
    __syncthreads();
    for (int off = 1; off < 1024; off <<= 1) {
        int t = (threadIdx.x >= (unsigned)off) ? s[threadIdx.x - off] : 0;
        __syncthreads();
        s[threadIdx.x] += t;
        __syncthreads();
    }
    if (i < n) g_rowptr[i] = s[threadIdx.x] - v;   // block-local exclusive
    if (threadIdx.x == 1023) g_bsum[blockIdx.x] = s[1023];
}

__global__ void scan2_kernel(int nb) {
    if (threadIdx.x == 0 && blockIdx.x == 0) {
        int run = 0;
        for (int b = 0; b < nb; b++) { int v = g_bsum[b]; g_bsum[b] = run; run += v; }
    }
}

__global__ void scan3_kernel(int n, int Etot) {
    int i = blockIdx.x * 1024 + threadIdx.x;
    if (i < n) {
        int v = g_rowptr[i] + g_bsum[blockIdx.x];
        g_rowptr[i] = v;
        g_cursor[i] = v;
    }
    if (i == 0) g_rowptr[n] = Etot;
}

__global__ void dinv_kernel(int n) {
    int i = blockIdx.x * blockDim.x + threadIdx.x;
    if (i < n) g_dinv[i] = rsqrtf((float)(g_cnt[i] + 1));   // +1 self loop
}

__global__ void fill_kernel(const void* __restrict__ ei, int E) {
    int e = blockIdx.x * blockDim.x + threadIdx.x;
    if (e >= E) return;
    int is64 = g_is64;
    int s = load_idx(ei, e, is64);
    int d = load_idx(ei, (long long)E + e, is64);
    int pos = atomicAdd(&g_cursor[d], 1);
    g_col[pos] = s;
}

// ---------------- GEMM: H[n,64] = X[n,K] @ W[K,64]  (fma.rn.f32x2) ---------
template <int K>
__global__ void gemm_kernel(const float* __restrict__ X, const float* __restrict__ W,
                            float* __restrict__ H, int nrows) {
    __shared__ __align__(16) float Ws[K * 64];
    for (int i = threadIdx.x; i < K * 64; i += blockDim.x) Ws[i] = W[i];
    __syncthreads();
    int row = blockIdx.x * blockDim.x + threadIdx.x;
    if (row >= nrows) return;

    unsigned long long acc[32];
#pragma unroll
    for (int j = 0; j < 32; j++) acc[j] = 0ull;

    const float4* xr = (const float4*)(X + (size_t)row * K);
#pragma unroll 1
    for (int kk = 0; kk < K / 4; kk++) {
        float4 xv = xr[kk];
        float xs[4] = {xv.x, xv.y, xv.z, xv.w};
#pragma unroll
        for (int u = 0; u < 4; u++) {
            int k = kk * 4 + u;
            unsigned long long xx;
            asm("mov.b64 %0, {%1, %1};" : "=l"(xx) : "f"(xs[u]));
            const ulonglong2* wrow = (const ulonglong2*)(Ws + k * 64);
#pragma unroll
            for (int q = 0; q < 16; q++) {
                ulonglong2 w = wrow[q];
                asm("fma.rn.f32x2 %0, %1, %2, %0;" : "+l"(acc[2 * q])     : "l"(xx), "l"(w.x));
                asm("fma.rn.f32x2 %0, %1, %2, %0;" : "+l"(acc[2 * q + 1]) : "l"(xx), "l"(w.y));
            }
        }
    }
    unsigned long long* orow = (unsigned long long*)(H + (size_t)row * 64);
#pragma unroll
    for (int j = 0; j < 32; j++) orow[j] = acc[j];
}

// ---------------- gather: out[d] = (relu?)(b + dinv_d^2*h[d] + sum msgs) ----
// One warp per destination node; lane holds 2 of 64 feature columns.
// Edge loop unrolled x2 for MLP.
__global__ void gather_kernel(const float* __restrict__ h, const float* __restrict__ bias,
                              float* __restrict__ out, int n, int do_relu) {
    int gw = (blockIdx.x * blockDim.x + threadIdx.x) >> 5;
    int lane = threadIdx.x & 31;
    if (gw >= n) return;
    int d = gw;
    float dd = g_dinv[d];
    const float2* hp = (const float2*)h;
    float2 bv = ((const float2*)bias)[lane];
    float2 hv = hp[(size_t)d * 32 + lane];
    float dd2 = dd * dd;
    float ax = bv.x + dd2 * hv.x;
    float ay = bv.y + dd2 * hv.y;
    float bx = 0.f, by = 0.f;
    int beg = g_rowptr[d], end = g_rowptr[d + 1];
    int e = beg;
    for (; e + 2 <= end; e += 2) {
        int s0 = g_col[e];
        int s1 = g_col[e + 1];
        float n0 = g_dinv[s0] * dd;
        float n1 = g_dinv[s1] * dd;
        float2 v0 = hp[(size_t)s0 * 32 + lane];
        float2 v1 = hp[(size_t)s1 * 32 + lane];
        ax += n0 * v0.x;
        ay += n0 * v0.y;
        bx += n1 * v1.x;
        by += n1 * v1.y;
    }
    if (e < end) {
        int s0 = g_col[e];
        float n0 = g_dinv[s0] * dd;
        float2 v0 = hp[(size_t)s0 * 32 + lane];
        ax += n0 * v0.x;
        ay += n0 * v0.y;
    }
    ax += bx;
    ay += by;
    if (do_relu) { ax = fmaxf(ax, 0.f); ay = fmaxf(ay, 0.f); }
    float2 r; r.x = ax; r.y = ay;
    ((float2*)out)[(size_t)d * 32 + lane] = r;
}

// ---------------- final: logits = emb @ Wl + bl; log_softmax ---------------
__global__ void final_kernel(const float* __restrict__ emb, const float* __restrict__ Wl,
                             const float* __restrict__ bl, float* __restrict__ out, int n) {
    __shared__ __align__(16) float Ws[64 * OUTD];
    __shared__ float bs[OUTD];
    for (int i = threadIdx.x; i < 64 * OUTD; i += blockDim.x) Ws[i] = Wl[i];
    if (threadIdx.x < OUTD) bs[threadIdx.x] = bl[threadIdx.x];
    __syncthreads();
    int row = blockIdx.x * blockDim.x + threadIdx.x;
    if (row >= n) return;

    float acc[OUTD];
#pragma unroll
    for (int j = 0; j < OUTD; j++) acc[j] = bs[j];

    const float4* xr = (const float4*)(emb + (size_t)row * 64);
#pragma unroll 1
    for (int kk = 0; kk < 16; kk++) {
        float4 xv = xr[kk];
        float xs[4] = {xv.x, xv.y, xv.z, xv.w};
#pragma unroll
        for (int u = 0; u < 4; u++) {
            int k = kk * 4 + u;
            float xk = xs[u];
            const float4* wrow = (const float4*)(Ws + k * OUTD);
#pragma unroll
            for (int q = 0; q < OUTD / 4; q++) {
                float4 w = wrow[q];
                acc[4 * q]     += xk * w.x;
                acc[4 * q + 1] += xk * w.y;
                acc[4 * q + 2] += xk * w.z;
                acc[4 * q + 3] += xk * w.w;
            }
        }
    }
    float m = acc[0];
#pragma unroll
    for (int j = 1; j < OUTD; j++) m = fmaxf(m, acc[j]);
    float ssum = 0.f;
#pragma unroll
    for (int j = 0; j < OUTD; j++) ssum += __expf(acc[j] - m);
    float lse = m + __logf(ssum);
    float* orow = out + (size_t)row * OUTD;
#pragma unroll
    for (int j = 0; j < OUTD; j++) orow[j] = acc[j] - lse;
}

// ---------------- launch -----------------------------------------------------
extern "C" void kernel_launch(void* const* d_in, const int* in_sizes, int n_in,
                              void* d_out, int out_size) {
    const float* x  = (const float*)d_in[0];
    const void*  ei = d_in[1];
    const float* W1 = (const float*)d_in[2];
    const float* b1 = (const float*)d_in[3];
    const float* W2 = (const float*)d_in[4];
    const float* b2 = (const float*)d_in[5];
    const float* Wl = (const float*)d_in[6];
    const float* bl = (const float*)d_in[7];
    float* out = (float*)d_out;

    int N = in_sizes[0] / IND;   // 100000
    int E = in_sizes[1] / 2;     // 1600000

    int nb = (N + 1023) / 1024;

    detect_kernel<<<1, 32>>>((const int*)ei);
    zero_cnt_kernel<<<(N + 255) / 256, 256>>>(N);
    count_kernel<<<(E + 255) / 256, 256>>>(ei, E);
    scan1_kernel<<<nb, 1024>>>(N);
    scan2_kernel<<<1, 32>>>(nb);
    scan3_kernel<<<nb, 1024>>>(N, E);
    dinv_kernel<<<(N + 255) / 256, 256>>>(N);
    fill_kernel<<<(E + 255) / 256, 256>>>(ei, E);

    // layer 1: h1 = relu(Â (x W1) + b1)
    gemm_kernel<IND><<<(N + 255) / 256, 256>>>(x, W1, g_bufA, N);
    gather_kernel<<<(N * 32 + 255) / 256, 256>>>(g_bufA, b1, g_bufB, N, 1);

    // layer 2: emb = Â (h1 W2) + b2
    gemm_kernel<HID><<<(N + 255) / 256, 256>>>(g_bufB, W2, g_bufA, N);
    gather_kernel<<<(N * 32 + 255) / 256, 256>>>(g_bufA, b2, g_bufB, N, 0);

    // classifier + log_softmax
    final_kernel<<<(N + 255) / 256, 256>>>(g_bufB, Wl, bl, out, N);
}

// round 5
// speedup vs baseline: 1.2577x; 1.2577x over previous
#include <cuda_runtime.h>
#include <cstdint>

#define NN 100000
#define EE 1600000
#define IND 128
#define HID 64
#define OUTD 40

// ---------------- scratch (device globals; no allocation allowed) -----------
__device__ float g_bufA[(size_t)NN * HID];   // gemm outputs (h1, then h2)
__device__ float g_bufB[(size_t)NN * HID];   // gather outputs (o1, then emb)
__device__ int   g_cnt[NN];
__device__ int   g_rowptr[NN + 1];
__device__ int   g_cursor[NN];
struct EdgeCW { int col; float w; };         // packed (src, norm) per CSR slot
__device__ EdgeCW g_cw[EE];
__device__ float g_dinv[NN];
__device__ int   g_bsum[256];
__device__ int   g_is64;

// ---------------- dtype detection for edge_index (int64 vs int32) ----------
__global__ void detect_kernel(const int* __restrict__ p) {
    if (blockIdx.x == 0 && threadIdx.x == 0) {
        int all0 = 1;
        for (int i = 1; i < 129; i += 2) {
            if (p[i] != 0) { all0 = 0; break; }
        }
        g_is64 = all0;   // node ids < 2^31, so an int64 view has zero hi-words
    }
}

__device__ __forceinline__ int load_idx(const void* p, long long i, int is64) {
    if (is64) return (int)((const long long*)p)[i];
    return ((const int*)p)[i];
}

// ---------------- degree / CSR build ----------------------------------------
__global__ void zero_cnt_kernel(int n) {
    int i = blockIdx.x * blockDim.x + threadIdx.x;
    if (i < n) g_cnt[i] = 0;
}

__global__ void count_kernel(const void* __restrict__ ei, int E) {
    int e = blockIdx.x * blockDim.x + threadIdx.x;
    if (e >= E) return;
    int is64 = g_is64;
    int d = load_idx(ei, (long long)E + e, is64);   // dst row
    atomicAdd(&g_cnt[d], 1);
}

__global__ void scan1_kernel(int n) {
    __shared__ int s[1024];
    int i = blockIdx.x * 1024 + threadIdx.x;
    int v = (i < n) ? g_cnt[i] : 0;
    s[threadIdx.x] = v;
    __syncthreads();
    for (int off = 1; off < 1024; off <<= 1) {
        int t = (threadIdx.x >= (unsigned)off) ? s[threadIdx.x - off] : 0;
        __syncthreads();
        s[threadIdx.x] += t;
        __syncthreads();
    }
    if (i < n) g_rowptr[i] = s[threadIdx.x] - v;   // block-local exclusive
    if (threadIdx.x == 1023) g_bsum[blockIdx.x] = s[1023];
}

__global__ void scan2_kernel(int nb) {
    if (threadIdx.x == 0 && blockIdx.x == 0) {
        int run = 0;
        for (int b = 0; b < nb; b++) { int v = g_bsum[b]; g_bsum[b] = run; run += v; }
    }
}

__global__ void scan3_kernel(int n, int Etot) {
    int i = blockIdx.x * 1024 + threadIdx.x;
    if (i < n) {
        int v = g_rowptr[i] + g_bsum[blockIdx.x];
        g_rowptr[i] = v;
        g_cursor[i] = v;
    }
    if (i == 0) g_rowptr[n] = Etot;
}

__global__ void dinv_kernel(int n) {
    int i = blockIdx.x * blockDim.x + threadIdx.x;
    if (i < n) g_dinv[i] = rsqrtf((float)(g_cnt[i] + 1));   // +1 self loop
}

// fill CSR slots with packed (src, dinv[src]*dinv[dst])
__global__ void fill_kernel(const void* __restrict__ ei, int E) {
    int e = blockIdx.x * blockDim.x + threadIdx.x;
    if (e >= E) return;
    int is64 = g_is64;
    int s = load_idx(ei, e, is64);
    int d = load_idx(ei, (long long)E + e, is64);
    int pos = atomicAdd(&g_cursor[d], 1);
    EdgeCW cw;
    cw.col = s;
    cw.w = __ldg(&g_dinv[s]) * __ldg(&g_dinv[d]);
    g_cw[pos] = cw;
}

// ---------------- GEMM: H[n,64] = X[n,K] @ W[K,64] --------------------------
// 2 threads per row; each computes 32 of the 64 output columns (32 fp32 accs).
template <int K>
__global__ void __launch_bounds__(256, 4)
gemm_kernel(const float* __restrict__ X, const float* __restrict__ W,
            float* __restrict__ H, int nrows) {
    __shared__ __align__(16) float Ws[K * 64];
    for (int i = threadIdx.x; i < K * 64; i += blockDim.x) Ws[i] = W[i];
    __syncthreads();
    int t = blockIdx.x * blockDim.x + threadIdx.x;
    int row = t >> 1;
    int half = (t & 1) * 32;
    if (row >= nrows) return;

    float acc[32];
#pragma unroll
    for (int j = 0; j < 32; j++) acc[j] = 0.f;

    const float4* xr = (const float4*)(X + (size_t)row * K);
#pragma unroll 4
    for (int kk = 0; kk < K / 4; kk++) {
        float4 xv = xr[kk];
        float xs[4] = {xv.x, xv.y, xv.z, xv.w};
#pragma unroll
        for (int u = 0; u < 4; u++) {
            int k = kk * 4 + u;
            const float4* wrow = (const float4*)(Ws + k * 64 + half);
#pragma unroll
            for (int q = 0; q < 8; q++) {
                float4 w = wrow[q];
                acc[4 * q]     += xs[u] * w.x;
                acc[4 * q + 1] += xs[u] * w.y;
                acc[4 * q + 2] += xs[u] * w.z;
                acc[4 * q + 3] += xs[u] * w.w;
            }
        }
    }
    float4* orow = (float4*)(H + (size_t)row * 64 + half);
#pragma unroll
    for (int q = 0; q < 8; q++) {
        float4 r;
        r.x = acc[4 * q]; r.y = acc[4 * q + 1]; r.z = acc[4 * q + 2]; r.w = acc[4 * q + 3];
        orow[q] = r;
    }
}

// ---------------- gather: out[d] = (relu?)(b + dinv_d^2*h[d] + sum msgs) ----
// One warp per destination node; lane holds 2 of 64 feature columns.
// Edge loop unrolled x4 with packed (col, norm) loads -> 2-deep dep chain.
__global__ void __launch_bounds__(256, 8)
gather_kernel(const float* __restrict__ h, const float* __restrict__ bias,
              float* __restrict__ out, int n, int do_relu) {
    int gw = (blockIdx.x * blockDim.x + threadIdx.x) >> 5;
    int lane = threadIdx.x & 31;
    if (gw >= n) return;
    int d = gw;
    float dd = g_dinv[d];
    const float2* hp = (const float2*)h;
    float2 bv = ((const float2*)bias)[lane];
    float2 hv = hp[(size_t)d * 32 + lane];
    float dd2 = dd * dd;
    float ax = bv.x + dd2 * hv.x;
    float ay = bv.y + dd2 * hv.y;
    float bx = 0.f, by = 0.f;
    float cx = 0.f, cy = 0.f;
    float ex = 0.f, ey = 0.f;
    int beg = g_rowptr[d], end = g_rowptr[d + 1];
    int e = beg;
    for (; e + 4 <= end; e += 4) {
        EdgeCW c0 = g_cw[e];
        EdgeCW c1 = g_cw[e + 1];
        EdgeCW c2 = g_cw[e + 2];
        EdgeCW c3 = g_cw[e + 3];
        float2 v0 = hp[(size_t)c0.col * 32 + lane];
        float2 v1 = hp[(size_t)c1.col * 32 + lane];
        float2 v2 = hp[(size_t)c2.col * 32 + lane];
        float2 v3 = hp[(size_t)c3.col * 32 + lane];
        ax += c0.w * v0.x;  ay += c0.w * v0.y;
        bx += c1.w * v1.x;  by += c1.w * v1.y;
        cx += c2.w * v2.x;  cy += c2.w * v2.y;
        ex += c3.w * v3.x;  ey += c3.w * v3.y;
    }
    for (; e < end; e++) {
        EdgeCW c0 = g_cw[e];
        float2 v0 = hp[(size_t)c0.col * 32 + lane];
        ax += c0.w * v0.x;
        ay += c0.w * v0.y;
    }
    ax += bx + cx + ex;
    ay += by + cy + ey;
    if (do_relu) { ax = fmaxf(ax, 0.f); ay = fmaxf(ay, 0.f); }
    float2 r; r.x = ax; r.y = ay;
    ((float2*)out)[(size_t)d * 32 + lane] = r;
}

// ---------------- final: logits = emb @ Wl + bl; log_softmax ---------------
__global__ void __launch_bounds__(256, 4)
final_kernel(const float* __restrict__ emb, const float* __restrict__ Wl,
             const float* __restrict__ bl, float* __restrict__ out, int n) {
    __shared__ __align__(16) float Ws[64 * OUTD];
    __shared__ float bs[OUTD];
    for (int i = threadIdx.x; i < 64 * OUTD; i += blockDim.x) Ws[i] = Wl[i];
    if (threadIdx.x < OUTD) bs[threadIdx.x] = bl[threadIdx.x];
    __syncthreads();
    int row = blockIdx.x * blockDim.x + threadIdx.x;
    if (row >= n) return;

    float acc[OUTD];
#pragma unroll
    for (int j = 0; j < OUTD; j++) acc[j] = bs[j];

    const float4* xr = (const float4*)(emb + (size_t)row * 64);
#pragma unroll 2
    for (int kk = 0; kk < 16; kk++) {
        float4 xv = xr[kk];
        float xs[4] = {xv.x, xv.y, xv.z, xv.w};
#pragma unroll
        for (int u = 0; u < 4; u++) {
            int k = kk * 4 + u;
            const float4* wrow = (const float4*)(Ws + k * OUTD);
#pragma unroll
            for (int q = 0; q < OUTD / 4; q++) {
                float4 w = wrow[q];
                acc[4 * q]     += xs[u] * w.x;
                acc[4 * q + 1] += xs[u] * w.y;
                acc[4 * q + 2] += xs[u] * w.z;
                acc[4 * q + 3] += xs[u] * w.w;
            }
        }
    }
    float m = acc[0];
#pragma unroll
    for (int j = 1; j < OUTD; j++) m = fmaxf(m, acc[j]);
    float ssum = 0.f;
#pragma unroll
    for (int j = 0; j < OUTD; j++) ssum += __expf(acc[j] - m);
    float lse = m + __logf(ssum);
    float* orow = out + (size_t)row * OUTD;
#pragma unroll
    for (int j = 0; j < OUTD; j++) orow[j] = acc[j] - lse;
}

// ---------------- launch -----------------------------------------------------
extern "C" void kernel_launch(void* const* d_in, const int* in_sizes, int n_in,
                              void* d_out, int out_size) {
    const float* x  = (const float*)d_in[0];
    const void*  ei = d_in[1];
    const float* W1 = (const float*)d_in[2];
    const float* b1 = (const float*)d_in[3];
    const float* W2 = (const float*)d_in[4];
    const float* b2 = (const float*)d_in[5];
    const float* Wl = (const float*)d_in[6];
    const float* bl = (const float*)d_in[7];
    float* out = (float*)d_out;

    int N = in_sizes[0] / IND;   // 100000
    int E = in_sizes[1] / 2;     // 1600000

    int nb = (N + 1023) / 1024;

    detect_kernel<<<1, 32>>>((const int*)ei);
    zero_cnt_kernel<<<(N + 255) / 256, 256>>>(N);
    count_kernel<<<(E + 255) / 256, 256>>>(ei, E);
    scan1_kernel<<<nb, 1024>>>(N);
    scan2_kernel<<<1, 32>>>(nb);
    scan3_kernel<<<nb, 1024>>>(N, E);
    dinv_kernel<<<(N + 255) / 256, 256>>>(N);
    fill_kernel<<<(E + 255) / 256, 256>>>(ei, E);

    // layer 1: o1 = relu(Â (x W1) + b1)
    gemm_kernel<IND><<<(N * 2 + 255) / 256, 256>>>(x, W1, g_bufA, N);
    gather_kernel<<<(N * 32 + 255) / 256, 256>>>(g_bufA, b1, g_bufB, N, 1);

    // layer 2: emb = Â (o1 W2) + b2
    gemm_kernel<HID><<<(N * 2 + 255) / 256, 256>>>(g_bufB, W2, g_bufA, N);
    gather_kernel<<<(N * 32 + 255) / 256, 256>>>(g_bufA, b2, g_bufB, N, 0);

    // classifier + log_softmax
    final_kernel<<<(N + 255) / 256, 256>>>(g_bufB, Wl, bl, out, N);
}